// round 15
// baseline (speedup 1.0000x reference)
#include <cuda_runtime.h>
#include <math.h>

#define N_NODES   20000
#define N_EDGES   320000
#define MUL0      64
#define NODE_DIM  240          // 64 + 3*32 + 5*16
#define NUM_BASIS 16
#define NCH       112          // 64 + 32 + 16 fused channels
#define NSTAT     144          // 9 * 16 sufficient statistics per node
#define INV_SQRT_MAXAT 0.0916698497028211f   // 1/sqrt(119)

// Fused projection matrices: M[b][ch] includes one_scalar and 1/sqrt(64)
__device__ float g_M[NUM_BASIS * NCH];
// Per-node sufficient statistics: G[n][j][b] = sum_e sh_e[j] * rbf_e[b]
__device__ float g_stats[(size_t)N_NODES * NSTAT];

// ---------------------------------------------------------------------------
// K1: blocks [0,8): fused M via coalesced smem staging of all weights.
//     blocks [8,600): zero g_stats (grid-stride; also L2 pre-warm for the
//     edge kernel's atomics — removing it cost +10us in R10).
// ---------------------------------------------------------------------------
#define M_BLOCKS   8
#define Z_BLOCKS   592
#define M_PER_BLK  (NUM_BASIS * NCH / M_BLOCKS)   // 224

__global__ void __launch_bounds__(256)
setup_kernel(const float* __restrict__ W_rbf,
             const float* __restrict__ w_expand,
             const float* __restrict__ b_expand,
             const float* __restrict__ Wp0,
             const float* __restrict__ Wp1,
             const float* __restrict__ Wp2)
{
    __shared__ float sCoef[NUM_BASIS * 192];   // 3072: W_rbf * (we+be)
    __shared__ float sWp[7168];                // Wp0[4096] | Wp1[2048] | Wp2[1024]

    int t = threadIdx.x;

    if (blockIdx.x < M_BLOCKS) {
        // coalesced staging
        for (int i = t; i < NUM_BASIS * 192; i += 256) {
            int j = i % 192;                   // 0..191; c = j & 63
            sCoef[i] = W_rbf[i] * (w_expand[j & 63] + b_expand[j & 63]);
        }
        for (int i = t; i < 4096; i += 256) sWp[i]        = Wp0[i];
        for (int i = t; i < 2048; i += 256) sWp[4096 + i] = Wp1[i];
        for (int i = t; i < 1024; i += 256) sWp[6144 + i] = Wp2[i];
        __syncthreads();

        for (int oi = t; oi < M_PER_BLK; oi += 256) {
            int w  = blockIdx.x * M_PER_BLK + oi;
            int b  = w / NCH;
            int ch = w % NCH;

            int roff, woff, K, d;
            if (ch < 64)      { roff = 0;   woff = 0;    K = 64; d = ch; }
            else if (ch < 96) { roff = 64;  woff = 4096; K = 32; d = ch - 64; }
            else              { roff = 128; woff = 6144; K = 16; d = ch - 96; }

            const float* cf = sCoef + b * 192 + roff;
            const float* wp = sWp + woff + d;
            float acc = 0.f;
            #pragma unroll 16
            for (int c = 0; c < 64; ++c)
                acc = fmaf(cf[c], wp[c * K], acc);
            g_M[b * NCH + ch] = acc * 0.125f;   // * 1/sqrt(64)
        }
    } else {
        // zero stats as float4 (also L2 pre-warm)
        const int n4 = N_NODES * NSTAT / 4;
        float4 z = make_float4(0.f, 0.f, 0.f, 0.f);
        int tid = (blockIdx.x - M_BLOCKS) * 256 + t;
        for (int i = tid; i < n4; i += Z_BLOCKS * 256)
            ((float4*)g_stats)[i] = z;
    }
}

// ---------------------------------------------------------------------------
// Vectorized L2 reduction
// ---------------------------------------------------------------------------
__device__ __forceinline__ void red_add_v4(float* addr, float a, float b, float c, float d)
{
    asm volatile("red.global.add.v4.f32 [%0], {%1,%2,%3,%4};"
                 :: "l"(addr), "f"(a), "f"(b), "f"(c), "f"(d) : "memory");
}

// ---------------------------------------------------------------------------
// K2: per-edge rbf + rsh (staged in smem), warp-cooperative coalesced stats
//     flush, then coalesced warp-region output stores (proven shape).
// ---------------------------------------------------------------------------
#define EK_THREADS 128
#define ROWSTRIDE  28          // floats; 112B, 16B-aligned

__global__ void __launch_bounds__(EK_THREADS)
edge_kernel(const float* __restrict__ pos,
            const int*   __restrict__ edge_index,
            float*       __restrict__ rbf_out,
            float*       __restrict__ rsh_out)
{
    __shared__ float sbuf[4][32][ROWSTRIDE];   // [warp][edge][0:16 rbf |16:25 sh]
    __shared__ int   sdst[4][32];

    int tid  = threadIdx.x;
    int warp = tid >> 5;
    int lane = tid & 31;
    int e = blockIdx.x * EK_THREADS + tid;

    bool active = false;
    float* mybuf = sbuf[warp][lane];

    {
        int src = edge_index[e];
        int dst = edge_index[N_EDGES + e];
        sdst[warp][lane] = dst;

        const float* Ps = pos + 3 * src;
        const float* Pd = pos + 3 * dst;
        // reference permutes pos columns to [1,2,0] before differencing
        float vx = Pd[1] - Ps[1];
        float vy = Pd[2] - Ps[2];
        float vz = Pd[0] - Ps[0];

        float d2   = vx * vx + vy * vy + vz * vz;
        float dist = sqrtf(d2);
        float dcl  = fmaxf(dist, 1e-8f);
        float uinv = 1.0f / dcl;
        float x = vx * uinv, y = vy * uinv, z = vz * uinv;

        const float s3  = 1.7320508075688772f;
        const float s5  = 2.23606797749979f;
        const float s15 = 3.872983346207417f;

        float sh[9];
        sh[0] = 1.f;
        sh[1] = s3 * x;
        sh[2] = s3 * y;
        sh[3] = s3 * z;
        sh[4] = s15 * x * z;
        sh[5] = s15 * x * y;
        sh[6] = s5 * (y * y - 0.5f * (x * x + z * z));
        sh[7] = s15 * y * z;
        sh[8] = 0.5f * s15 * (z * z - x * x);

        float rbf[16];
        active = (dcl < 5.0f);
        if (active) {
            float X  = dcl * 0.2f;
            float X2 = X * X;
            float X5 = X2 * X2 * X;
            float fc = 1.0f + X5 * (-21.0f + X * (35.0f - 15.0f * X));
            float theta = 3.14159265358979323846f * X;
            // precise sinf/cosf: MUFU fast path destroys tiny theta
            // (self-loop edges, d ~ 1e-8) via fixed-point argument granularity
            float s1 = sinf(theta), c1 = cosf(theta);
            float two  = 2.0f * c1;
            float pref = 0.6324555320336759f * uinv * fc;   // sqrt(2/5)/d * fc
            float sp = 0.f, s = s1;
            #pragma unroll
            for (int n = 0; n < 16; ++n) {
                rbf[n] = pref * s;
                float sn = two * s - sp;
                sp = s; s = sn;
            }
        } else {
            #pragma unroll
            for (int n = 0; n < 16; ++n) rbf[n] = 0.f;
        }

        #pragma unroll
        for (int i = 0; i < 16; ++i) mybuf[i] = rbf[i];
        #pragma unroll
        for (int j = 0; j < 9; ++j)  mybuf[16 + j] = sh[j];
    }

    unsigned act = __ballot_sync(0xffffffffu, active);
    __syncwarp();

    // warp-cooperative flush: one edge at a time, coalesced red.v4
    while (act) {
        int k = __ffs(act) - 1;
        act &= act - 1;
        const float* eb = sbuf[warp][k];
        float* S = g_stats + (size_t)sdst[warp][k] * NSTAT;

        float  sj = eb[16 + (lane >> 2)];
        float4 r  = *(const float4*)(eb + ((lane & 3) << 2));
        red_add_v4(S + 4 * lane, sj * r.x, sj * r.y, sj * r.z, sj * r.w);

        if (lane < 4) {
            float  s8 = eb[24];
            float4 r2 = *(const float4*)(eb + (lane << 2));
            red_add_v4(S + 128 + 4 * lane, s8 * r2.x, s8 * r2.y, s8 * r2.z, s8 * r2.w);
        }
    }

    // coalesced output stores from staged smem (warp-contiguous regions)
    {
        size_t ebase = (size_t)blockIdx.x * EK_THREADS + warp * 32;

        float4* dst4 = (float4*)(rbf_out + ebase * 16);
        #pragma unroll
        for (int k4 = 0; k4 < 4; ++k4) {
            int k = lane + 32 * k4;                         // 0..127
            const float* srcp = sbuf[warp][k >> 2] + ((k & 3) << 2);
            dst4[k] = *(const float4*)srcp;
        }

        float* dsts = rsh_out + ebase * 9;
        #pragma unroll
        for (int k = 0; k < 9; ++k) {
            int idx = lane + 32 * k;                        // 0..287
            int e9 = idx / 9;
            int c9 = idx - 9 * e9;
            dsts[idx] = sbuf[warp][e9][16 + c9];
        }
    }
}

// ---------------------------------------------------------------------------
// K3: node projection, M in registers, G consumed as LDS.128.
//     128 threads/block = 120 half-tasks (2 output columns each), NB=4.
// ---------------------------------------------------------------------------
#define NB              4      // nodes per sync round
#define NODES_PER_BLOCK 32

__device__ __forceinline__ void task_desc(int t, int& goff, int& moff,
                                          int& chbase, int& stride)
{
    if (t < 16) {             // path0: e0 cols 4t..4t+3
        goff = 0; moff = 4 * t; chbase = 4 * t; stride = 1;
    } else if (t < 40) {      // path1: m = p>>3, g = p&7
        int p = t - 16, m = p >> 3, g = p & 7;
        goff = (1 + m) * 16; moff = 64 + 4 * g;
        chbase = 64 + 12 * g + m; stride = 3;
    } else {                  // path2: m = p>>2, g = p&3
        int p = t - 40, m = p >> 2, g = p & 3;
        goff = (4 + m) * 16; moff = 96 + 4 * g;
        chbase = 160 + 20 * g + m; stride = 5;
    }
}

__global__ void __launch_bounds__(128)
node_kernel(const int*   __restrict__ at_no,
            const float* __restrict__ W_atom,
            const float* __restrict__ b_atom,
            float*       __restrict__ node_emb)
{
    __shared__ __align__(16) float sG[NB * NSTAT];   // 4 nodes x 144

    int t = threadIdx.x;
    bool tvalid = (t < 120);

    int task = t >> 1, half = t & 1;
    int goff = 0, moff = 0, chbase = 0, stride = 1;
    if (tvalid) task_desc(task, goff, moff, chbase, stride);
    int col0 = moff + 2 * half;                        // M columns col0, col0+1
    int ch0  = chbase + (2 * half) * stride;
    int ch1  = chbase + (2 * half + 1) * stride;

    // preload M columns + (path0) b_atom pair into registers
    float m0[16], m1[16];
    float2 ba = make_float2(0.f, 0.f);
    if (tvalid) {
        #pragma unroll
        for (int b = 0; b < 16; ++b) {
            m0[b] = g_M[b * NCH + col0];
            m1[b] = g_M[b * NCH + col0 + 1];
        }
        if (t < 32) ba = *(const float2*)(b_atom + ch0);
    }

    int nbase0 = blockIdx.x * NODES_PER_BLOCK;

    for (int it = 0; it < NODES_PER_BLOCK / NB; ++it) {
        int nbase = nbase0 + it * NB;

        __syncthreads();   // previous round's sG fully consumed
        {
            const float4* Sp = (const float4*)(g_stats + (size_t)nbase * NSTAT);
            float4* Dp = (float4*)sG;
            Dp[t] = Sp[t];                                     // 0..127
            if (t < 16) Dp[128 + t] = Sp[128 + t];             // 128..143
        }
        __syncthreads();

        if (tvalid) {
            #pragma unroll
            for (int k = 0; k < NB; ++k) {
                int n = nbase + k;
                // G slice is 16B-aligned: k*144 and goff both multiples of 16
                const float4* G4 = (const float4*)(sG + k * NSTAT + goff);
                float a0 = 0.f, a1 = 0.f;
                #pragma unroll
                for (int q = 0; q < 4; ++q) {
                    float4 g = G4[q];
                    a0 = fmaf(g.x, m0[4*q+0], a0); a1 = fmaf(g.x, m1[4*q+0], a1);
                    a0 = fmaf(g.y, m0[4*q+1], a0); a1 = fmaf(g.y, m1[4*q+1], a1);
                    a0 = fmaf(g.z, m0[4*q+2], a0); a1 = fmaf(g.z, m1[4*q+2], a1);
                    a0 = fmaf(g.w, m0[4*q+3], a0); a1 = fmaf(g.w, m1[4*q+3], a1);
                }
                float* nrow = node_emb + (size_t)n * NODE_DIM;
                if (t < 32) {
                    // path0: ch0 = 2t, ch1 = 2t+1 consecutive -> float2
                    int an = at_no[n];
                    float2 wa = *(const float2*)(W_atom + an * MUL0 + ch0);
                    a0 += fmaf(wa.x, INV_SQRT_MAXAT, ba.x);
                    a1 += fmaf(wa.y, INV_SQRT_MAXAT, ba.y);
                    *(float2*)(nrow + ch0) = make_float2(a0, a1);
                } else {
                    nrow[ch0] = a0;
                    nrow[ch1] = a1;
                }
            }
        }
    }
}

// ---------------------------------------------------------------------------
// Launch
// ---------------------------------------------------------------------------
extern "C" void kernel_launch(void* const* d_in, const int* in_sizes, int n_in,
                              void* d_out, int out_size)
{
    const int*   at_no      = (const int*)  d_in[0];
    const float* pos        = (const float*)d_in[1];
    const int*   edge_index = (const int*)  d_in[2];
    const float* W_atom     = (const float*)d_in[3];
    const float* b_atom     = (const float*)d_in[4];
    const float* w_expand   = (const float*)d_in[5];
    const float* b_expand   = (const float*)d_in[6];
    const float* W_rbf      = (const float*)d_in[7];
    const float* Wp0        = (const float*)d_in[8];
    const float* Wp1        = (const float*)d_in[9];
    const float* Wp2        = (const float*)d_in[10];

    float* out      = (float*)d_out;
    float* node_emb = out;                                   // 20000*240
    float* rbf_out  = out + (size_t)N_NODES * NODE_DIM;      // 320000*16
    float* rsh_out  = rbf_out + (size_t)N_EDGES * NUM_BASIS; // 320000*9

    setup_kernel<<<M_BLOCKS + Z_BLOCKS, 256>>>(W_rbf, w_expand, b_expand,
                                               Wp0, Wp1, Wp2);
    edge_kernel<<<N_EDGES / EK_THREADS, EK_THREADS>>>(
        pos, edge_index, rbf_out, rsh_out);
    node_kernel<<<N_NODES / NODES_PER_BLOCK, 128>>>(at_no, W_atom, b_atom, node_emb);
}

// round 16
// speedup vs baseline: 1.1069x; 1.1069x over previous
#include <cuda_runtime.h>
#include <math.h>

#define N_NODES   20000
#define N_EDGES   320000
#define MUL0      64
#define NODE_DIM  240          // 64 + 3*32 + 5*16
#define NUM_BASIS 16
#define NCH       112          // 64 + 32 + 16 fused channels
#define NSTAT     144          // 9 * 16 sufficient statistics per node
#define INV_SQRT_MAXAT 0.0916698497028211f   // 1/sqrt(119)

// Fused projection matrices: M[b][ch] includes one_scalar and 1/sqrt(64)
__device__ float g_M[NUM_BASIS * NCH];
// Per-node sufficient statistics: G[n][j][b] = sum_e sh_e[j] * rbf_e[b]
__device__ float g_stats[(size_t)N_NODES * NSTAT];

// ---------------------------------------------------------------------------
// K1: precompute fused M (first 1792 warps, short+wide shuffle shape — the
//     only setup shape that stays at ~6.4us) + zero stats (grid-stride;
//     also pre-warms g_stats into L2 for edge_kernel's atomics).
// ---------------------------------------------------------------------------
__global__ void __launch_bounds__(256)
setup_kernel(const float* __restrict__ W_rbf,
             const float* __restrict__ w_expand,
             const float* __restrict__ b_expand,
             const float* __restrict__ Wp0,
             const float* __restrict__ Wp1,
             const float* __restrict__ Wp2)
{
    int tid = blockIdx.x * blockDim.x + threadIdx.x;

    // ---- fused M first: one warp per output element ----
    int w    = tid >> 5;
    int lane = threadIdx.x & 31;
    if (w < NUM_BASIS * NCH) {
        int b  = w / NCH;
        int ch = w % NCH;

        int   roff;
        const float* Wp;
        int   K, d;
        if (ch < 64)       { roff = 0;   Wp = Wp0; K = 64; d = ch; }
        else if (ch < 96)  { roff = 64;  Wp = Wp1; K = 32; d = ch - 64; }
        else               { roff = 128; Wp = Wp2; K = 16; d = ch - 96; }

        float acc = 0.f;
        #pragma unroll
        for (int h = 0; h < 2; ++h) {
            int c = lane + 32 * h;
            acc = fmaf(W_rbf[b * 192 + roff + c] * (w_expand[c] + b_expand[c]),
                       Wp[c * K + d], acc);
        }
        #pragma unroll
        for (int off = 16; off > 0; off >>= 1)
            acc += __shfl_xor_sync(0xffffffffu, acc, off);

        if (lane == 0) g_M[b * NCH + ch] = acc * 0.125f;   // * 1/sqrt(64)
    }

    // ---- zero stats as float4 ----
    const int n4 = N_NODES * NSTAT / 4;
    float4 z = make_float4(0.f, 0.f, 0.f, 0.f);
    for (int i = tid; i < n4; i += gridDim.x * blockDim.x)
        ((float4*)g_stats)[i] = z;
}

// ---------------------------------------------------------------------------
// Vectorized L2 reduction
// ---------------------------------------------------------------------------
__device__ __forceinline__ void red_add_v4(float* addr, float a, float b, float c, float d)
{
    asm volatile("red.global.add.v4.f32 [%0], {%1,%2,%3,%4};"
                 :: "l"(addr), "f"(a), "f"(b), "f"(c), "f"(d) : "memory");
}

// ---------------------------------------------------------------------------
// K2: per-edge rbf + rsh (staged in smem), warp-cooperative coalesced stats
//     flush, then coalesced warp-region output stores (proven shape).
// ---------------------------------------------------------------------------
#define EK_THREADS 128
#define ROWSTRIDE  28          // floats; 112B, 16B-aligned

__global__ void __launch_bounds__(EK_THREADS)
edge_kernel(const float* __restrict__ pos,
            const int*   __restrict__ edge_index,
            float*       __restrict__ rbf_out,
            float*       __restrict__ rsh_out)
{
    __shared__ float sbuf[4][32][ROWSTRIDE];   // [warp][edge][0:16 rbf |16:25 sh]
    __shared__ int   sdst[4][32];

    int tid  = threadIdx.x;
    int warp = tid >> 5;
    int lane = tid & 31;
    int e = blockIdx.x * EK_THREADS + tid;

    bool active = false;
    float* mybuf = sbuf[warp][lane];

    {
        int src = edge_index[e];
        int dst = edge_index[N_EDGES + e];
        sdst[warp][lane] = dst;

        const float* Ps = pos + 3 * src;
        const float* Pd = pos + 3 * dst;
        // reference permutes pos columns to [1,2,0] before differencing
        float vx = Pd[1] - Ps[1];
        float vy = Pd[2] - Ps[2];
        float vz = Pd[0] - Ps[0];

        float d2   = vx * vx + vy * vy + vz * vz;
        float dist = sqrtf(d2);
        float dcl  = fmaxf(dist, 1e-8f);
        float uinv = 1.0f / dcl;
        float x = vx * uinv, y = vy * uinv, z = vz * uinv;

        const float s3  = 1.7320508075688772f;
        const float s5  = 2.23606797749979f;
        const float s15 = 3.872983346207417f;

        float sh[9];
        sh[0] = 1.f;
        sh[1] = s3 * x;
        sh[2] = s3 * y;
        sh[3] = s3 * z;
        sh[4] = s15 * x * z;
        sh[5] = s15 * x * y;
        sh[6] = s5 * (y * y - 0.5f * (x * x + z * z));
        sh[7] = s15 * y * z;
        sh[8] = 0.5f * s15 * (z * z - x * x);

        float rbf[16];
        active = (dcl < 5.0f);
        if (active) {
            float X  = dcl * 0.2f;
            float X2 = X * X;
            float X5 = X2 * X2 * X;
            float fc = 1.0f + X5 * (-21.0f + X * (35.0f - 15.0f * X));
            float theta = 3.14159265358979323846f * X;
            // precise sinf/cosf: MUFU fast path destroys tiny theta
            // (self-loop edges, d ~ 1e-8) via fixed-point argument granularity
            float s1 = sinf(theta), c1 = cosf(theta);
            float two  = 2.0f * c1;
            float pref = 0.6324555320336759f * uinv * fc;   // sqrt(2/5)/d * fc
            float sp = 0.f, s = s1;
            #pragma unroll
            for (int n = 0; n < 16; ++n) {
                rbf[n] = pref * s;
                float sn = two * s - sp;
                sp = s; s = sn;
            }
        } else {
            #pragma unroll
            for (int n = 0; n < 16; ++n) rbf[n] = 0.f;
        }

        #pragma unroll
        for (int i = 0; i < 16; ++i) mybuf[i] = rbf[i];
        #pragma unroll
        for (int j = 0; j < 9; ++j)  mybuf[16 + j] = sh[j];
    }

    unsigned act = __ballot_sync(0xffffffffu, active);
    __syncwarp();

    // warp-cooperative flush: one edge at a time, coalesced red.v4
    while (act) {
        int k = __ffs(act) - 1;
        act &= act - 1;
        const float* eb = sbuf[warp][k];
        float* S = g_stats + (size_t)sdst[warp][k] * NSTAT;

        float  sj = eb[16 + (lane >> 2)];
        float4 r  = *(const float4*)(eb + ((lane & 3) << 2));
        red_add_v4(S + 4 * lane, sj * r.x, sj * r.y, sj * r.z, sj * r.w);

        if (lane < 4) {
            float  s8 = eb[24];
            float4 r2 = *(const float4*)(eb + (lane << 2));
            red_add_v4(S + 128 + 4 * lane, s8 * r2.x, s8 * r2.y, s8 * r2.z, s8 * r2.w);
        }
    }

    // coalesced output stores from staged smem (warp-contiguous regions)
    {
        size_t ebase = (size_t)blockIdx.x * EK_THREADS + warp * 32;

        float4* dst4 = (float4*)(rbf_out + ebase * 16);
        #pragma unroll
        for (int k4 = 0; k4 < 4; ++k4) {
            int k = lane + 32 * k4;                         // 0..127
            const float* srcp = sbuf[warp][k >> 2] + ((k & 3) << 2);
            dst4[k] = *(const float4*)srcp;
        }

        float* dsts = rsh_out + ebase * 9;
        #pragma unroll
        for (int k = 0; k < 9; ++k) {
            int idx = lane + 32 * k;                        // 0..287
            int e9 = idx / 9;
            int c9 = idx - 9 * e9;
            dsts[idx] = sbuf[warp][e9][16 + c9];
        }
    }
}

// ---------------------------------------------------------------------------
// K3: node projection, M in registers, G consumed as LDS.128 (R15 shape:
//     measured ~3.8us vs 15.4us scalar).
//     128 threads/block = 120 half-tasks (2 output columns each), NB=4.
// ---------------------------------------------------------------------------
#define NB              4      // nodes per sync round
#define NODES_PER_BLOCK 32

__device__ __forceinline__ void task_desc(int t, int& goff, int& moff,
                                          int& chbase, int& stride)
{
    if (t < 16) {             // path0: e0 cols 4t..4t+3
        goff = 0; moff = 4 * t; chbase = 4 * t; stride = 1;
    } else if (t < 40) {      // path1: m = p>>3, g = p&7
        int p = t - 16, m = p >> 3, g = p & 7;
        goff = (1 + m) * 16; moff = 64 + 4 * g;
        chbase = 64 + 12 * g + m; stride = 3;
    } else {                  // path2: m = p>>2, g = p&3
        int p = t - 40, m = p >> 2, g = p & 3;
        goff = (4 + m) * 16; moff = 96 + 4 * g;
        chbase = 160 + 20 * g + m; stride = 5;
    }
}

__global__ void __launch_bounds__(128)
node_kernel(const int*   __restrict__ at_no,
            const float* __restrict__ W_atom,
            const float* __restrict__ b_atom,
            float*       __restrict__ node_emb)
{
    __shared__ __align__(16) float sG[NB * NSTAT];   // 4 nodes x 144

    int t = threadIdx.x;
    bool tvalid = (t < 120);

    int task = t >> 1, half = t & 1;
    int goff = 0, moff = 0, chbase = 0, stride = 1;
    if (tvalid) task_desc(task, goff, moff, chbase, stride);
    int col0 = moff + 2 * half;                        // M columns col0, col0+1
    int ch0  = chbase + (2 * half) * stride;
    int ch1  = chbase + (2 * half + 1) * stride;

    // preload M columns + (path0) b_atom pair into registers
    float m0[16], m1[16];
    float2 ba = make_float2(0.f, 0.f);
    if (tvalid) {
        #pragma unroll
        for (int b = 0; b < 16; ++b) {
            m0[b] = g_M[b * NCH + col0];
            m1[b] = g_M[b * NCH + col0 + 1];
        }
        if (t < 32) ba = *(const float2*)(b_atom + ch0);
    }

    int nbase0 = blockIdx.x * NODES_PER_BLOCK;

    for (int it = 0; it < NODES_PER_BLOCK / NB; ++it) {
        int nbase = nbase0 + it * NB;

        __syncthreads();   // previous round's sG fully consumed
        {
            const float4* Sp = (const float4*)(g_stats + (size_t)nbase * NSTAT);
            float4* Dp = (float4*)sG;
            Dp[t] = Sp[t];                                     // 0..127
            if (t < 16) Dp[128 + t] = Sp[128 + t];             // 128..143
        }
        __syncthreads();

        if (tvalid) {
            #pragma unroll
            for (int k = 0; k < NB; ++k) {
                int n = nbase + k;
                // G slice is 16B-aligned: k*144 and goff both multiples of 16
                const float4* G4 = (const float4*)(sG + k * NSTAT + goff);
                float a0 = 0.f, a1 = 0.f;
                #pragma unroll
                for (int q = 0; q < 4; ++q) {
                    float4 g = G4[q];
                    a0 = fmaf(g.x, m0[4*q+0], a0); a1 = fmaf(g.x, m1[4*q+0], a1);
                    a0 = fmaf(g.y, m0[4*q+1], a0); a1 = fmaf(g.y, m1[4*q+1], a1);
                    a0 = fmaf(g.z, m0[4*q+2], a0); a1 = fmaf(g.z, m1[4*q+2], a1);
                    a0 = fmaf(g.w, m0[4*q+3], a0); a1 = fmaf(g.w, m1[4*q+3], a1);
                }
                float* nrow = node_emb + (size_t)n * NODE_DIM;
                if (t < 32) {
                    // path0: ch0 = 2t, ch1 = 2t+1 consecutive -> float2
                    int an = at_no[n];
                    float2 wa = *(const float2*)(W_atom + an * MUL0 + ch0);
                    a0 += fmaf(wa.x, INV_SQRT_MAXAT, ba.x);
                    a1 += fmaf(wa.y, INV_SQRT_MAXAT, ba.y);
                    *(float2*)(nrow + ch0) = make_float2(a0, a1);
                } else {
                    nrow[ch0] = a0;
                    nrow[ch1] = a1;
                }
            }
        }
    }
}

// ---------------------------------------------------------------------------
// Launch
// ---------------------------------------------------------------------------
extern "C" void kernel_launch(void* const* d_in, const int* in_sizes, int n_in,
                              void* d_out, int out_size)
{
    const int*   at_no      = (const int*)  d_in[0];
    const float* pos        = (const float*)d_in[1];
    const int*   edge_index = (const int*)  d_in[2];
    const float* W_atom     = (const float*)d_in[3];
    const float* b_atom     = (const float*)d_in[4];
    const float* w_expand   = (const float*)d_in[5];
    const float* b_expand   = (const float*)d_in[6];
    const float* W_rbf      = (const float*)d_in[7];
    const float* Wp0        = (const float*)d_in[8];
    const float* Wp1        = (const float*)d_in[9];
    const float* Wp2        = (const float*)d_in[10];

    float* out      = (float*)d_out;
    float* node_emb = out;                                   // 20000*240
    float* rbf_out  = out + (size_t)N_NODES * NODE_DIM;      // 320000*16
    float* rsh_out  = rbf_out + (size_t)N_EDGES * NUM_BASIS; // 320000*9

    setup_kernel<<<224, 256>>>(W_rbf, w_expand, b_expand, Wp0, Wp1, Wp2);
    edge_kernel<<<N_EDGES / EK_THREADS, EK_THREADS>>>(
        pos, edge_index, rbf_out, rsh_out);
    node_kernel<<<N_NODES / NODES_PER_BLOCK, 128>>>(at_no, W_atom, b_atom, node_emb);
}